// round 1
// baseline (speedup 1.0000x reference)
#include <cuda_runtime.h>
#include <cuda_bf16.h>

// SinkhornMixer: M = sigmoid(L) + I; 5x { row-normalize; col-normalize }.
// Reformulated as M = diag(r) * A * diag(c), A = S + I read-only.
//   row step: r_i <- r_i / (r_i * (S c + c)_i + eps)
//   col step: c_j <- c_j / (c_j * (S^T r + r)_j + eps)
// Final: out_ij = r_i * (S_ij + (i==j)) * c_j

#define N 8192
#define N4 (N / 4)            // 2048 float4 per row
#define EPS 1e-6f
#define COL_ROWS_PB 128       // rows per block in column matvec

__device__ float g_S[(size_t)N * N];   // 256 MB scratch (module-scope, allowed)
__device__ float g_r[N];
__device__ float g_c[N];
__device__ float g_z[N];

// ---- block reduction helper -------------------------------------------------
__device__ __forceinline__ float block_reduce_sum(float v) {
    __shared__ float sm[8];
    int lane = threadIdx.x & 31;
    int wid  = threadIdx.x >> 5;
    #pragma unroll
    for (int off = 16; off > 0; off >>= 1)
        v += __shfl_down_sync(0xffffffffu, v, off);
    if (lane == 0) sm[wid] = v;
    __syncthreads();
    if (wid == 0) {
        v = (lane < 8) ? sm[lane] : 0.0f;
        #pragma unroll
        for (int off = 4; off > 0; off >>= 1)
            v += __shfl_down_sync(0xffffffffu, v, off);
    }
    return v;  // valid in thread 0
}

// ---- pass 0: S = sigmoid(L), fused first row step (c == 1) ------------------
// rowsum_i(M0) = sum_j S_ij + 1  ->  r_i = 1 / (rowsum + eps); c_i = 1; z_i = 0
__global__ void __launch_bounds__(256) k_sigmoid_row(const float* __restrict__ L) {
    int row = blockIdx.x;
    const float4* Lr = (const float4*)(L + (size_t)row * N);
    float4*       Sr = (float4*)(g_S + (size_t)row * N);
    int t = threadIdx.x;
    float acc = 0.0f;
    #pragma unroll
    for (int k = 0; k < 8; k++) {
        float4 v = Lr[t + k * 256];
        float4 s;
        s.x = 1.0f / (1.0f + __expf(-v.x));
        s.y = 1.0f / (1.0f + __expf(-v.y));
        s.z = 1.0f / (1.0f + __expf(-v.z));
        s.w = 1.0f / (1.0f + __expf(-v.w));
        acc += (s.x + s.y) + (s.z + s.w);
        Sr[t + k * 256] = s;
    }
    float tot = block_reduce_sum(acc);
    if (t == 0) {
        float y = tot + 1.0f;              // + c_i with c = 1
        g_r[row] = 1.0f / (y + EPS);       // r was 1
        g_c[row] = 1.0f;
        g_z[row] = 0.0f;
    }
}

// ---- row matvec + r update (iterations 2..5) --------------------------------
__global__ void __launch_bounds__(256) k_row() {
    int row = blockIdx.x;
    const float4* Sr = (const float4*)(g_S + (size_t)row * N);
    const float4* C4 = (const float4*)g_c;
    int t = threadIdx.x;
    float acc = 0.0f;
    #pragma unroll
    for (int k = 0; k < 8; k++) {
        float4 s = Sr[t + k * 256];
        float4 c = C4[t + k * 256];
        acc += s.x * c.x + s.y * c.y + s.z * c.z + s.w * c.w;
    }
    float tot = block_reduce_sum(acc);
    if (t == 0) {
        float y  = tot + g_c[row];         // identity contribution
        float rv = g_r[row];
        g_r[row] = rv / (rv * y + EPS);
        g_z[row] = 0.0f;                   // prep next col matvec
    }
}

// ---- column matvec: z_j += sum_{i in chunk} S_ij * r_i ----------------------
__global__ void __launch_bounds__(256) k_col() {
    __shared__ float rs[COL_ROWS_PB];
    int t = threadIdx.x;
    int col4 = blockIdx.x * 256 + t;                 // float4 column index
    int i0 = blockIdx.y * COL_ROWS_PB;
    if (t < COL_ROWS_PB) rs[t] = g_r[i0 + t];
    __syncthreads();

    const float4* S4 = (const float4*)g_S;
    float4 acc = make_float4(0.f, 0.f, 0.f, 0.f);
    #pragma unroll 4
    for (int i = 0; i < COL_ROWS_PB; i++) {
        float rv = rs[i];
        float4 s = S4[(size_t)(i0 + i) * N4 + col4];
        acc.x += s.x * rv;
        acc.y += s.y * rv;
        acc.z += s.z * rv;
        acc.w += s.w * rv;
    }
    int j = col4 * 4;
    atomicAdd(&g_z[j + 0], acc.x);
    atomicAdd(&g_z[j + 1], acc.y);
    atomicAdd(&g_z[j + 2], acc.z);
    atomicAdd(&g_z[j + 3], acc.w);
}

// ---- c update ---------------------------------------------------------------
__global__ void __launch_bounds__(256) k_updc() {
    int j = blockIdx.x * 256 + threadIdx.x;
    if (j < N) {
        float u  = g_z[j] + g_r[j];        // identity contribution
        float cv = g_c[j];
        g_c[j] = cv / (cv * u + EPS);
    }
}

// ---- final: out_ij = r_i * (S_ij + (i==j)) * c_j ----------------------------
__global__ void __launch_bounds__(256) k_final(float* __restrict__ out) {
    int row = blockIdx.x;
    float ri = g_r[row];
    const float4* Sr = (const float4*)(g_S + (size_t)row * N);
    const float4* C4 = (const float4*)g_c;
    float4*       Or = (float4*)(out + (size_t)row * N);
    int t = threadIdx.x;
    int diag4 = row >> 2;                  // float4 group holding the diagonal
    int diagc = row & 3;
    #pragma unroll
    for (int k = 0; k < 8; k++) {
        int idx = t + k * 256;
        float4 s = Sr[idx];
        float4 c = C4[idx];
        float4 o;
        o.x = ri * s.x * c.x;
        o.y = ri * s.y * c.y;
        o.z = ri * s.z * c.z;
        o.w = ri * s.w * c.w;
        if (idx == diag4) {
            float add = ri * ((const float*)C4)[row];
            if (diagc == 0) o.x += add;
            else if (diagc == 1) o.y += add;
            else if (diagc == 2) o.z += add;
            else o.w += add;
        }
        Or[idx] = o;
    }
}

extern "C" void kernel_launch(void* const* d_in, const int* in_sizes, int n_in,
                              void* d_out, int out_size) {
    const float* L = (const float*)d_in[0];
    float* out = (float*)d_out;

    dim3 colGrid(N4 / 256, N / COL_ROWS_PB);   // (8, 64)

    // Iteration 1 row step fused with sigmoid precompute
    k_sigmoid_row<<<N, 256>>>(L);
    k_col<<<colGrid, 256>>>();
    k_updc<<<N / 256, 256>>>();

    // Iterations 2..5
    for (int it = 1; it < 5; it++) {
        k_row<<<N, 256>>>();
        k_col<<<colGrid, 256>>>();
        k_updc<<<N / 256, 256>>>();
    }

    k_final<<<N, 256>>>(out);
}

// round 2
// speedup vs baseline: 1.1522x; 1.1522x over previous
#include <cuda_runtime.h>
#include <cuda_fp16.h>

// SinkhornMixer: M = sigmoid(L) + I; 5x { row-normalize; col-normalize }.
// M = diag(r) * A * diag(c), A = S + I read-only.
// S stored in fp16 (only feeds matvecs -> r,c; averaged rounding error ~1e-5).
// Final output recomputes sigmoid(L) in fp32 for full accuracy.

#define N 8192
#define EPS 1e-6f
#define COL_ROWS_PB 128
#define ROW_U4 (N / 8)        // 1024 uint4 (8 halves) per row

__device__ __half g_S[(size_t)N * N];   // 128 MB fp16 scratch
__device__ float g_r[N];
__device__ float g_c[N];
__device__ float g_z[N];

// ---- block reduction --------------------------------------------------------
__device__ __forceinline__ float block_reduce_sum(float v) {
    __shared__ float sm[8];
    int lane = threadIdx.x & 31;
    int wid  = threadIdx.x >> 5;
    #pragma unroll
    for (int off = 16; off > 0; off >>= 1)
        v += __shfl_down_sync(0xffffffffu, v, off);
    if (lane == 0) sm[wid] = v;
    __syncthreads();
    if (wid == 0) {
        v = (lane < 8) ? sm[lane] : 0.0f;
        #pragma unroll
        for (int off = 4; off > 0; off >>= 1)
            v += __shfl_down_sync(0xffffffffu, v, off);
    }
    return v;  // thread 0
}

// ---- pass 0: S16 = sigmoid(L), fused first row step (c == 1) ----------------
__global__ void __launch_bounds__(256) k_sigmoid_row(const float* __restrict__ L) {
    int row = blockIdx.x;
    const float4* Lr = (const float4*)(L + (size_t)row * N);
    uint2*        Sr = (uint2*)(g_S + (size_t)row * N);   // 4 halves per uint2
    int t = threadIdx.x;
    float acc = 0.0f;
    #pragma unroll
    for (int k = 0; k < 8; k++) {
        float4 v = Lr[t + k * 256];
        float sx = 1.0f / (1.0f + __expf(-v.x));
        float sy = 1.0f / (1.0f + __expf(-v.y));
        float sz = 1.0f / (1.0f + __expf(-v.z));
        float sw = 1.0f / (1.0f + __expf(-v.w));
        acc += (sx + sy) + (sz + sw);
        __half2 h01 = __floats2half2_rn(sx, sy);
        __half2 h23 = __floats2half2_rn(sz, sw);
        uint2 p;
        p.x = *(unsigned int*)&h01;
        p.y = *(unsigned int*)&h23;
        Sr[t + k * 256] = p;
    }
    float tot = block_reduce_sum(acc);
    if (t == 0) {
        float y = tot + 1.0f;
        g_r[row] = 1.0f / (y + EPS);
        g_c[row] = 1.0f;
        g_z[row] = 0.0f;
    }
}

// ---- row matvec + r update --------------------------------------------------
__global__ void __launch_bounds__(256) k_row() {
    int row = blockIdx.x;
    const uint4*  Sr = (const uint4*)(g_S + (size_t)row * N);  // 8 halves each
    const float4* C4 = (const float4*)g_c;
    int t = threadIdx.x;
    float acc = 0.0f;
    #pragma unroll
    for (int k = 0; k < 4; k++) {
        int idx = t + k * 256;                 // uint4 index within row
        uint4 s = Sr[idx];
        float4 c0 = C4[idx * 2];
        float4 c1 = C4[idx * 2 + 1];
        float2 f0 = __half22float2(*(const __half2*)&s.x);
        float2 f1 = __half22float2(*(const __half2*)&s.y);
        float2 f2 = __half22float2(*(const __half2*)&s.z);
        float2 f3 = __half22float2(*(const __half2*)&s.w);
        acc += f0.x * c0.x + f0.y * c0.y + f1.x * c0.z + f1.y * c0.w
             + f2.x * c1.x + f2.y * c1.y + f3.x * c1.z + f3.y * c1.w;
    }
    float tot = block_reduce_sum(acc);
    if (t == 0) {
        float y  = tot + g_c[row];
        float rv = g_r[row];
        g_r[row] = rv / (rv * y + EPS);
        g_z[row] = 0.0f;
    }
}

// ---- column matvec: z_j += sum_i S_ij * r_i ---------------------------------
__global__ void __launch_bounds__(256) k_col() {
    __shared__ float rs[COL_ROWS_PB];
    int t = threadIdx.x;
    int colu = blockIdx.x * 256 + t;           // uint4 (8-half) column group
    int i0 = blockIdx.y * COL_ROWS_PB;
    if (t < COL_ROWS_PB) rs[t] = g_r[i0 + t];
    __syncthreads();

    const uint4* S4 = (const uint4*)g_S;       // row stride = ROW_U4
    float a0 = 0.f, a1 = 0.f, a2 = 0.f, a3 = 0.f,
          a4 = 0.f, a5 = 0.f, a6 = 0.f, a7 = 0.f;
    #pragma unroll 4
    for (int i = 0; i < COL_ROWS_PB; i++) {
        float rv = rs[i];
        uint4 s = S4[(size_t)(i0 + i) * ROW_U4 + colu];
        float2 f0 = __half22float2(*(const __half2*)&s.x);
        float2 f1 = __half22float2(*(const __half2*)&s.y);
        float2 f2 = __half22float2(*(const __half2*)&s.z);
        float2 f3 = __half22float2(*(const __half2*)&s.w);
        a0 += f0.x * rv;  a1 += f0.y * rv;
        a2 += f1.x * rv;  a3 += f1.y * rv;
        a4 += f2.x * rv;  a5 += f2.y * rv;
        a6 += f3.x * rv;  a7 += f3.y * rv;
    }
    int j = colu * 8;
    atomicAdd(&g_z[j + 0], a0);
    atomicAdd(&g_z[j + 1], a1);
    atomicAdd(&g_z[j + 2], a2);
    atomicAdd(&g_z[j + 3], a3);
    atomicAdd(&g_z[j + 4], a4);
    atomicAdd(&g_z[j + 5], a5);
    atomicAdd(&g_z[j + 6], a6);
    atomicAdd(&g_z[j + 7], a7);
}

// ---- c update ---------------------------------------------------------------
__global__ void __launch_bounds__(256) k_updc() {
    int j = blockIdx.x * 256 + threadIdx.x;
    if (j < N) {
        float u  = g_z[j] + g_r[j];
        float cv = g_c[j];
        g_c[j] = cv / (cv * u + EPS);
    }
}

// ---- final: out_ij = r_i * (sigmoid(L_ij) + (i==j)) * c_j  (full fp32) ------
__global__ void __launch_bounds__(256) k_final(const float* __restrict__ L,
                                               float* __restrict__ out) {
    int row = blockIdx.x;
    float ri = g_r[row];
    const float4* Lr = (const float4*)(L + (size_t)row * N);
    const float4* C4 = (const float4*)g_c;
    float4*       Or = (float4*)(out + (size_t)row * N);
    int t = threadIdx.x;
    int diag4 = row >> 2;
    int diagc = row & 3;
    #pragma unroll
    for (int k = 0; k < 8; k++) {
        int idx = t + k * 256;
        float4 v = Lr[idx];
        float4 c = C4[idx];
        float4 o;
        o.x = ri * (1.0f / (1.0f + __expf(-v.x))) * c.x;
        o.y = ri * (1.0f / (1.0f + __expf(-v.y))) * c.y;
        o.z = ri * (1.0f / (1.0f + __expf(-v.z))) * c.z;
        o.w = ri * (1.0f / (1.0f + __expf(-v.w))) * c.w;
        if (idx == diag4) {
            float add = ri * ((const float*)C4)[row];
            if (diagc == 0) o.x += add;
            else if (diagc == 1) o.y += add;
            else if (diagc == 2) o.z += add;
            else o.w += add;
        }
        Or[idx] = o;
    }
}

extern "C" void kernel_launch(void* const* d_in, const int* in_sizes, int n_in,
                              void* d_out, int out_size) {
    const float* L = (const float*)d_in[0];
    float* out = (float*)d_out;

    dim3 colGrid(ROW_U4 / 256, N / COL_ROWS_PB);   // (4, 64)

    k_sigmoid_row<<<N, 256>>>(L);      // S16 + first row step (c = 1)
    k_col<<<colGrid, 256>>>();
    k_updc<<<N / 256, 256>>>();

    for (int it = 1; it < 5; it++) {
        k_row<<<N, 256>>>();
        k_col<<<colGrid, 256>>>();
        k_updc<<<N / 256, 256>>>();
    }

    k_final<<<N, 256>>>(L, out);
}

// round 3
// speedup vs baseline: 1.4971x; 1.2993x over previous
#include <cuda_runtime.h>
#include <cuda_fp16.h>

// SinkhornMixer: M = sigmoid(L) + I; 5x { row norm; col norm }.
// M = diag(r)*(S+I)*diag(c); S quantized to u8 (64MB -> fully L2-resident).
// s ~= (q+0.5)/256 ; matvecs use raw q dot + 0.5*vecsum correction.
// Final output recomputes sigmoid(L) in fp32 (no quantization on output path).

#define N 8192
#define EPS 1e-6f
#define CROWS 128      // rows per block, col matvec
#define RROWS 4        // rows per block, row matvec

__device__ unsigned char g_S8[(size_t)N * N];  // 64 MB
__device__ float  g_r[N];
__device__ float  g_c[N];
__device__ __half g_c16[N];
__device__ float  g_z[N];
__device__ float  g_rsum;   // sum of r (for col-step 0.5 correction)
__device__ float  g_csum;   // sum of c (for row-step 0.5 correction)

// ---- block reduction (256 threads) ------------------------------------------
__device__ __forceinline__ float block_reduce_sum(float v) {
    __shared__ float sm[8];
    int lane = threadIdx.x & 31;
    int wid  = threadIdx.x >> 5;
    #pragma unroll
    for (int off = 16; off > 0; off >>= 1)
        v += __shfl_down_sync(0xffffffffu, v, off);
    if (lane == 0) sm[wid] = v;
    __syncthreads();
    if (wid == 0) {
        v = (lane < 8) ? sm[lane] : 0.0f;
        #pragma unroll
        for (int off = 4; off > 0; off >>= 1)
            v += __shfl_down_sync(0xffffffffu, v, off);
    }
    return v;  // thread 0
}

__device__ __forceinline__ float sigmoidf(float x) {
    return 1.0f / (1.0f + __expf(-x));
}

// ---- pass 0: S8 = quant(sigmoid(L)); exact fp32 rowsum -> first row step ----
__global__ void __launch_bounds__(256) k_sigmoid_row(const float* __restrict__ L) {
    int row = blockIdx.x;
    const float4* Lr = (const float4*)(L + (size_t)row * N);
    unsigned int* Sr = (unsigned int*)(g_S8 + (size_t)row * N);  // 2048 u32
    int t = threadIdx.x;
    float acc = 0.0f;
    #pragma unroll
    for (int k = 0; k < 8; k++) {
        float4 v = __ldcs(&Lr[t + k * 256]);
        float s0 = sigmoidf(v.x), s1 = sigmoidf(v.y);
        float s2 = sigmoidf(v.z), s3 = sigmoidf(v.w);
        acc += (s0 + s1) + (s2 + s3);
        unsigned q0 = min(255u, (unsigned)(s0 * 256.0f));
        unsigned q1 = min(255u, (unsigned)(s1 * 256.0f));
        unsigned q2 = min(255u, (unsigned)(s2 * 256.0f));
        unsigned q3 = min(255u, (unsigned)(s3 * 256.0f));
        Sr[t + k * 256] = q0 | (q1 << 8) | (q2 << 16) | (q3 << 24);
    }
    float tot = block_reduce_sum(acc);
    if (t == 0) {
        float y  = tot + 1.0f;             // identity (c=1)
        float rv = 1.0f / (y + EPS);       // r was 1
        g_r[row] = rv;
        atomicAdd(&g_rsum, rv);
        g_c[row]   = 1.0f;
        g_c16[row] = __float2half_rn(1.0f);
        g_z[row]   = 0.0f;
    }
}

// ---- col matvec: z_j += sum_i q_ij * r_i  (raw dot) -------------------------
__global__ void __launch_bounds__(256) k_col() {
    __shared__ float rs[CROWS];
    int t  = threadIdx.x;
    int cu = blockIdx.x * 256 + t;               // u32 column group (4 cols)
    int i0 = blockIdx.y * CROWS;
    for (int i = t; i < CROWS; i += 256) rs[i] = g_r[i0 + i];
    __syncthreads();

    const unsigned int* S = (const unsigned int*)g_S8;  // row stride 2048 u32
    float a0 = 0.f, a1 = 0.f, a2 = 0.f, a3 = 0.f;
    #pragma unroll 4
    for (int i = 0; i < CROWS; i++) {
        unsigned int w = S[(size_t)(i0 + i) * (N / 4) + cu];
        float rv = rs[i];
        a0 += (float)(w & 0xffu)         * rv;
        a1 += (float)((w >> 8) & 0xffu)  * rv;
        a2 += (float)((w >> 16) & 0xffu) * rv;
        a3 += (float)(w >> 24)           * rv;
    }
    int j = cu * 4;
    atomicAdd(&g_z[j + 0], a0);
    atomicAdd(&g_z[j + 1], a1);
    atomicAdd(&g_z[j + 2], a2);
    atomicAdd(&g_z[j + 3], a3);
}

// ---- c update (single block): u = z/256 + R/512 + r_j -----------------------
__global__ void __launch_bounds__(256) k_updc() {
    int t = threadIdx.x;
    float R  = g_rsum;
    float cs = 0.0f;
    for (int j = t; j < N; j += 256) {
        float u  = g_z[j] * (1.0f / 256.0f) + R * (1.0f / 512.0f) + g_r[j];
        float cv = g_c[j];
        float cn = cv / (cv * u + EPS);
        g_c[j]   = cn;
        g_c16[j] = __float2half_rn(cn);
        cs += cn;
    }
    float tot = block_reduce_sum(cs);
    if (t == 0) { g_csum = tot; g_rsum = 0.0f; }
}

// ---- row matvec (4 rows/block) + r update -----------------------------------
__global__ void __launch_bounds__(256) k_row() {
    int r0 = blockIdx.x * RROWS;
    int t  = threadIdx.x;
    const uint4* C16 = (const uint4*)g_c16;      // 1024 uint4 (8 halves each)
    float acc[RROWS] = {0.f, 0.f, 0.f, 0.f};

    #pragma unroll
    for (int k = 0; k < 2; k++) {
        int u = t + k * 256;                     // uint4 chunk (16 cols) of 512
        uint4 ca = C16[2 * u];
        uint4 cb = C16[2 * u + 1];
        float cf[16];
        {
            float2 f;
            f = __half22float2(*(const __half2*)&ca.x); cf[0]=f.x;  cf[1]=f.y;
            f = __half22float2(*(const __half2*)&ca.y); cf[2]=f.x;  cf[3]=f.y;
            f = __half22float2(*(const __half2*)&ca.z); cf[4]=f.x;  cf[5]=f.y;
            f = __half22float2(*(const __half2*)&ca.w); cf[6]=f.x;  cf[7]=f.y;
            f = __half22float2(*(const __half2*)&cb.x); cf[8]=f.x;  cf[9]=f.y;
            f = __half22float2(*(const __half2*)&cb.y); cf[10]=f.x; cf[11]=f.y;
            f = __half22float2(*(const __half2*)&cb.z); cf[12]=f.x; cf[13]=f.y;
            f = __half22float2(*(const __half2*)&cb.w); cf[14]=f.x; cf[15]=f.y;
        }
        #pragma unroll
        for (int rr = 0; rr < RROWS; rr++) {
            const uint4* Sr = (const uint4*)(g_S8 + (size_t)(r0 + rr) * N);
            uint4 s = Sr[u];
            unsigned int w;
            float a = acc[rr];
            w = s.x;
            a += (float)(w & 0xffu) * cf[0]  + (float)((w >> 8) & 0xffu) * cf[1]
               + (float)((w >> 16) & 0xffu) * cf[2]  + (float)(w >> 24) * cf[3];
            w = s.y;
            a += (float)(w & 0xffu) * cf[4]  + (float)((w >> 8) & 0xffu) * cf[5]
               + (float)((w >> 16) & 0xffu) * cf[6]  + (float)(w >> 24) * cf[7];
            w = s.z;
            a += (float)(w & 0xffu) * cf[8]  + (float)((w >> 8) & 0xffu) * cf[9]
               + (float)((w >> 16) & 0xffu) * cf[10] + (float)(w >> 24) * cf[11];
            w = s.w;
            a += (float)(w & 0xffu) * cf[12] + (float)((w >> 8) & 0xffu) * cf[13]
               + (float)((w >> 16) & 0xffu) * cf[14] + (float)(w >> 24) * cf[15];
            acc[rr] = a;
        }
    }

    // reduce 4 accumulators
    __shared__ float sm[8 * RROWS];
    int lane = t & 31, wid = t >> 5;
    #pragma unroll
    for (int rr = 0; rr < RROWS; rr++) {
        float v = acc[rr];
        #pragma unroll
        for (int off = 16; off > 0; off >>= 1)
            v += __shfl_down_sync(0xffffffffu, v, off);
        if (lane == 0) sm[wid * RROWS + rr] = v;
    }
    __syncthreads();
    if (t < RROWS) {
        float tot = 0.0f;
        #pragma unroll
        for (int w = 0; w < 8; w++) tot += sm[w * RROWS + t];
        int row = r0 + t;
        float y  = tot * (1.0f / 256.0f) + g_csum * (1.0f / 512.0f) + g_c[row];
        float rv = g_r[row];
        float rn = rv / (rv * y + EPS);
        g_r[row] = rn;
        atomicAdd(&g_rsum, rn);
        g_z[row] = 0.0f;                 // prep next col matvec
    }
}

// ---- final: out_ij = r_i * (sigmoid(L_ij) + (i==j)) * c_j  (full fp32) ------
__global__ void __launch_bounds__(256) k_final(const float* __restrict__ L,
                                               float* __restrict__ out) {
    int row = blockIdx.x;
    float ri = g_r[row];
    const float4* Lr = (const float4*)(L + (size_t)row * N);
    const float4* C4 = (const float4*)g_c;
    float4*       Or = (float4*)(out + (size_t)row * N);
    int t = threadIdx.x;
    int diag4 = row >> 2;
    int diagc = row & 3;
    #pragma unroll
    for (int k = 0; k < 8; k++) {
        int idx = t + k * 256;
        float4 v = __ldcs(&Lr[idx]);
        float4 c = C4[idx];
        float4 o;
        o.x = ri * sigmoidf(v.x) * c.x;
        o.y = ri * sigmoidf(v.y) * c.y;
        o.z = ri * sigmoidf(v.z) * c.z;
        o.w = ri * sigmoidf(v.w) * c.w;
        if (idx == diag4) {
            float add = ri * ((const float*)C4)[row];
            if (diagc == 0) o.x += add;
            else if (diagc == 1) o.y += add;
            else if (diagc == 2) o.z += add;
            else o.w += add;
        }
        __stcs(&Or[idx], o);
    }
}

extern "C" void kernel_launch(void* const* d_in, const int* in_sizes, int n_in,
                              void* d_out, int out_size) {
    const float* L = (const float*)d_in[0];
    float* out = (float*)d_out;

    dim3 colGrid(N / 4 / 256, N / CROWS);   // (8, 64)

    k_sigmoid_row<<<N, 256>>>(L);           // S8 + first row step (c = 1)
    k_col<<<colGrid, 256>>>();
    k_updc<<<1, 256>>>();

    for (int it = 1; it < 5; it++) {
        k_row<<<N / RROWS, 256>>>();
        k_col<<<colGrid, 256>>>();
        k_updc<<<1, 256>>>();
    }

    k_final<<<N, 256>>>(L, out);
}